// round 1
// baseline (speedup 1.0000x reference)
#include <cuda_runtime.h>
#include <math.h>

// Problem dims
#define BB 32
#define TT 1024
#define II 512
#define HH 1024

// Persistent-kernel config
#define GCTA 128      // CTAs (<= #SMs so all co-resident -> grid barrier is safe)
#define NTHREADS 256  // = 4 (k-split) * 8 (j per CTA) * 8 (b-quads)
#define JPC 8         // neurons (j) per CTA: 128*8 = 1024 = H

// ---------------- device global scratch (no cudaMalloc allowed) ----------------
__device__ float g_xT[(size_t)TT * II * BB];   // x transposed to [t][i][b], 64MB
__device__ float g_h0buf[2][HH * BB];          // layer0 hidden, [k][b] layout, ping-pong
__device__ float g_h1buf[2][HH * BB];          // layer1 hidden, [k][b] layout, ping-pong
__device__ unsigned g_cnt = 0;                 // grid barrier arrival counter
__device__ unsigned g_gen = 0;                 // grid barrier generation

// ---------------- grid-wide barrier (sense via generation counter) -------------
__device__ __forceinline__ void gridbar() {
    __syncthreads();
    if (threadIdx.x == 0) {
        __threadfence();  // make this CTA's global writes visible device-wide
        unsigned g = *((volatile unsigned*)&g_gen);
        unsigned a = atomicAdd(&g_cnt, 1u);
        if (a == GCTA - 1u) {
            g_cnt = 0u;
            __threadfence();
            atomicExch(&g_gen, g + 1u);
        } else {
            while (*((volatile unsigned*)&g_gen) == g) { }
        }
    }
    __syncthreads();
}

// ---------------- prologue: transpose x (B,T,I) -> xT[t][i][b] -----------------
__global__ void k_transpose_x(const float* __restrict__ x) {
    __shared__ float tile[32][33];
    int t = blockIdx.y;
    int i0 = blockIdx.x * 32;
    int lane = threadIdx.x;   // 32
    int row = threadIdx.y;    // 8
#pragma unroll
    for (int r = 0; r < 4; r++) {
        int b = row * 4 + r;
        tile[b][lane] = x[((size_t)b * TT + t) * II + i0 + lane];
    }
    __syncthreads();
#pragma unroll
    for (int r = 0; r < 4; r++) {
        int ii = row * 4 + r;
        g_xT[((size_t)t * II + i0 + ii) * BB + lane] = tile[lane][ii];
    }
}

// ---------------- prologue: h0 (2,B,H) -> [k][b] ping buffers ------------------
__global__ void k_init_h(const float* __restrict__ h0) {
    int idx = blockIdx.x * blockDim.x + threadIdx.x;  // over H*B (k-major)
    if (idx < HH * BB) {
        int k = idx / BB;
        int b = idx % BB;
        g_h0buf[0][idx] = h0[(size_t)0 * BB * HH + (size_t)b * HH + k];
        g_h1buf[0][idx] = h0[(size_t)1 * BB * HH + (size_t)b * HH + k];
    }
}

// ---------------- main persistent kernel ---------------------------------------
__global__ void __launch_bounds__(NTHREADS, 1) k_esgp(
    const float* __restrict__ W_in0, const float* __restrict__ W_res0,
    const float* __restrict__ W_z0,  const float* __restrict__ U_z0,
    const float* __restrict__ b_z0,
    const float* __restrict__ W_in1, const float* __restrict__ W_res1,
    const float* __restrict__ W_z1,  const float* __restrict__ U_z1,
    const float* __restrict__ b_z1,
    float* __restrict__ out)
{
    const int tid = threadIdx.x;
    const int kh = tid >> 6;          // 0..3  k-split (uniform per warp-pair)
    const int jj = (tid >> 3) & 7;    // 0..7  neuron within CTA
    const int bq = tid & 7;           // 0..7  batch quad (b = bq*4 .. bq*4+3)
    const int cta = blockIdx.x;
    const int j = cta * JPC + jj;     // global neuron index
    const int lid = jj * 8 + bq;      // 0..63

    __shared__ float s_red[4][64][8];
    __shared__ float s_out[8][32];

    const float4* __restrict__ wz0p = (const float4*)(W_z0  + (size_t)j * II);
    const float4* __restrict__ wi0p = (const float4*)(W_in0 + (size_t)j * II);
    const float4* __restrict__ uz0p = (const float4*)(U_z0   + (size_t)j * HH);
    const float4* __restrict__ wr0p = (const float4*)(W_res0 + (size_t)j * HH);
    const float4* __restrict__ wz1p = (const float4*)(W_z1   + (size_t)j * HH);
    const float4* __restrict__ uz1p = (const float4*)(U_z1   + (size_t)j * HH);
    const float4* __restrict__ wi1p = (const float4*)(W_in1  + (size_t)j * HH);
    const float4* __restrict__ wr1p = (const float4*)(W_res1 + (size_t)j * HH);
    const float bz0 = b_z0[j];
    const float bz1 = b_z1[j];

    for (int t = 0; t < TT; t++) {
        const int cur = t & 1;
        const int nxt = cur ^ 1;

        // ================= layer 0 =================
        float az[4], ah[4];
#pragma unroll
        for (int c = 0; c < 4; c++) { az[c] = 0.f; ah[c] = 0.f; }

        // ---- x projection part (K = I = 512, this thread: 128 of them) ----
        {
            const float4* __restrict__ xp = (const float4*)(g_xT + (size_t)t * II * BB);
            const int i4b = kh * 32;
#pragma unroll 4
            for (int i4 = i4b; i4 < i4b + 32; ++i4) {
                float4 wz = wz0p[i4];
                float4 wi = wi0p[i4];
                const float* wzf = (const float*)&wz;
                const float* wif = (const float*)&wi;
#pragma unroll
                for (int c = 0; c < 4; c++) {
                    float4 xv = xp[(size_t)(i4 * 4 + c) * 8 + bq];
                    az[0] += wzf[c] * xv.x; az[1] += wzf[c] * xv.y;
                    az[2] += wzf[c] * xv.z; az[3] += wzf[c] * xv.w;
                    ah[0] += wif[c] * xv.x; ah[1] += wif[c] * xv.y;
                    ah[2] += wif[c] * xv.z; ah[3] += wif[c] * xv.w;
                }
            }
        }
        // ---- recurrent part (K = H = 1024, this thread: 256 of them) ----
        {
            const float4* __restrict__ hb = (const float4*)(g_h0buf[cur]);
            const int k4b = kh * 64;
#pragma unroll 4
            for (int k4 = k4b; k4 < k4b + 64; ++k4) {
                float4 uz = uz0p[k4];
                float4 wr = wr0p[k4];
                const float* uzf = (const float*)&uz;
                const float* wrf = (const float*)&wr;
#pragma unroll
                for (int c = 0; c < 4; c++) {
                    float4 hv = hb[(size_t)(k4 * 4 + c) * 8 + bq];
                    az[0] += uzf[c] * hv.x; az[1] += uzf[c] * hv.y;
                    az[2] += uzf[c] * hv.z; az[3] += uzf[c] * hv.w;
                    ah[0] += wrf[c] * hv.x; ah[1] += wrf[c] * hv.y;
                    ah[2] += wrf[c] * hv.z; ah[3] += wrf[c] * hv.w;
                }
            }
        }
        // ---- k-split reduction + elementwise ----
#pragma unroll
        for (int c = 0; c < 4; c++) {
            s_red[kh][lid][c]     = az[c];
            s_red[kh][lid][4 + c] = ah[c];
        }
        __syncthreads();
        if (kh == 0) {
#pragma unroll
            for (int c = 0; c < 4; c++) {
                float vz = s_red[0][lid][c] + s_red[1][lid][c] + s_red[2][lid][c] + s_red[3][lid][c];
                float vh = s_red[0][lid][4+c] + s_red[1][lid][4+c] + s_red[2][lid][4+c] + s_red[3][lid][4+c];
                int b = bq * 4 + c;
                float z  = 1.f / (1.f + expf(-(vz + bz0)));
                float ht = tanhf(vh);
                float hc = g_h0buf[cur][j * BB + b];
                g_h0buf[nxt][j * BB + b] = (1.f - z) * hc + z * ht;
            }
        }
        gridbar();  // layer-0 state fully published

        // ================= layer 1 =================
#pragma unroll
        for (int c = 0; c < 4; c++) { az[c] = 0.f; ah[c] = 0.f; }
        {
            const float4* __restrict__ h0n = (const float4*)(g_h0buf[nxt]);
            const float4* __restrict__ h1c = (const float4*)(g_h1buf[cur]);
            const int k4b = kh * 64;
#pragma unroll 2
            for (int k4 = k4b; k4 < k4b + 64; ++k4) {
                float4 a = wz1p[k4];
                float4 u = uz1p[k4];
                float4 wi = wi1p[k4];
                float4 wr = wr1p[k4];
                const float* af = (const float*)&a;
                const float* uf = (const float*)&u;
                const float* inf_ = (const float*)&wi;
                const float* rf = (const float*)&wr;
#pragma unroll
                for (int c = 0; c < 4; c++) {
                    float4 p = h0n[(size_t)(k4 * 4 + c) * 8 + bq];
                    float4 q = h1c[(size_t)(k4 * 4 + c) * 8 + bq];
                    az[0] += af[c] * p.x + uf[c] * q.x;
                    az[1] += af[c] * p.y + uf[c] * q.y;
                    az[2] += af[c] * p.z + uf[c] * q.z;
                    az[3] += af[c] * p.w + uf[c] * q.w;
                    ah[0] += inf_[c] * p.x + rf[c] * q.x;
                    ah[1] += inf_[c] * p.y + rf[c] * q.y;
                    ah[2] += inf_[c] * p.z + rf[c] * q.z;
                    ah[3] += inf_[c] * p.w + rf[c] * q.w;
                }
            }
        }
#pragma unroll
        for (int c = 0; c < 4; c++) {
            s_red[kh][lid][c]     = az[c];
            s_red[kh][lid][4 + c] = ah[c];
        }
        __syncthreads();
        if (kh == 0) {
#pragma unroll
            for (int c = 0; c < 4; c++) {
                float vz = s_red[0][lid][c] + s_red[1][lid][c] + s_red[2][lid][c] + s_red[3][lid][c];
                float vh = s_red[0][lid][4+c] + s_red[1][lid][4+c] + s_red[2][lid][4+c] + s_red[3][lid][4+c];
                int b = bq * 4 + c;
                float z  = 1.f / (1.f + expf(-(vz + bz1)));
                float ht = tanhf(vh);
                float hc = g_h1buf[cur][j * BB + b];
                float hn = (1.f - z) * hc + z * ht;
                g_h1buf[nxt][j * BB + b] = hn;
                s_out[jj][b] = hn;
            }
        }
        __syncthreads();
        // coalesced-ish output write: out[b][t][cta*8 + je]
        {
            int b = tid >> 3;
            int je = tid & 7;
            out[((size_t)b * TT + t) * HH + cta * JPC + je] = s_out[je][b];
        }
        gridbar();  // layer-1 state fully published
    }

    // ---- h_n tail: (2, B, H) appended after output. Final state sits in buf[0]
    // (T=1024 is even: last write was nxt = (1023+1)&1 = 0). Each CTA owns its j slice.
    {
        int b = tid >> 3;
        int je = tid & 7;
        int jg = cta * JPC + je;
        const size_t base = (size_t)BB * TT * HH;
        out[base + (size_t)b * HH + jg]                      = g_h0buf[0][jg * BB + b];
        out[base + (size_t)BB * HH + (size_t)b * HH + jg]    = g_h1buf[0][jg * BB + b];
    }
}

// ---------------- launcher ------------------------------------------------------
extern "C" void kernel_launch(void* const* d_in, const int* in_sizes, int n_in,
                              void* d_out, int out_size) {
    const float* x      = (const float*)d_in[0];
    const float* h0     = (const float*)d_in[1];
    const float* W_in0  = (const float*)d_in[2];
    const float* W_res0 = (const float*)d_in[3];
    const float* W_z0   = (const float*)d_in[4];
    const float* U_z0   = (const float*)d_in[5];
    const float* b_z0   = (const float*)d_in[6];
    const float* W_in1  = (const float*)d_in[7];
    const float* W_res1 = (const float*)d_in[8];
    const float* W_z1   = (const float*)d_in[9];
    const float* U_z1   = (const float*)d_in[10];
    const float* b_z1   = (const float*)d_in[11];
    float* out = (float*)d_out;

    dim3 tb(32, 8);
    dim3 tg(II / 32, TT);
    k_transpose_x<<<tg, tb>>>(x);
    k_init_h<<<(HH * BB + 255) / 256, 256>>>(h0);
    k_esgp<<<GCTA, NTHREADS>>>(W_in0, W_res0, W_z0, U_z0, b_z0,
                               W_in1, W_res1, W_z1, U_z1, b_z1, out);
}

// round 2
// speedup vs baseline: 1.1986x; 1.1986x over previous
#include <cuda_runtime.h>
#include <math.h>

#define BB 32
#define TT 1024
#define II 512
#define HH 1024
#define GCTA 128
#define NTHREADS 256
#define JPC 8

typedef unsigned long long ull;

// ---------------- device global scratch ----------------
__device__ float  g_xT[(size_t)TT * II * BB];        // x transposed [t][i][b]
__device__ float4 g_wT4[(size_t)GCTA * 14336];       // weights per-CTA [k4][j][4]
__device__ float  g_h0buf[2][HH * BB];               // layer0 h, [k][b], ping-pong
__device__ float  g_h1buf[2][HH * BB];               // layer1 h, [k][b], ping-pong
__device__ unsigned g_cnt = 0;
__device__ unsigned g_gen = 0;

// ---------------- packed f32x2 helpers ----------------
__device__ __forceinline__ ull dup2(float w) {
    ull r; asm("mov.b64 %0, {%1, %1};" : "=l"(r) : "f"(w)); return r;
}
__device__ __forceinline__ void ffma2(ull &d, ull a, ull b) {
    asm("fma.rn.f32x2 %0, %1, %2, %0;" : "+l"(d) : "l"(a), "l"(b));
}
union F4 { float4 v; ull u[2]; float f[4]; };
union F2U { ull u; float2 f; };

// ---------------- grid barrier (release/acquire) ----------------
__device__ __forceinline__ void gridbar() {
    __syncthreads();
    if (threadIdx.x == 0) {
        __threadfence();                      // release: CTA's writes -> L2 visible
        unsigned g = *((volatile unsigned*)&g_gen);
        unsigned a = atomicAdd(&g_cnt, 1u);
        if (a == GCTA - 1u) {
            g_cnt = 0u;
            __threadfence();
            atomicExch(&g_gen, g + 1u);
        } else {
            while (*((volatile unsigned*)&g_gen) == g) { }
        }
        __threadfence();                      // acquire side
    }
    __syncthreads();
}

// ---------------- prologue: transpose x (B,T,I) -> xT[t][i][b] ----------------
__global__ void k_transpose_x(const float* __restrict__ x) {
    __shared__ float tile[32][33];
    int t = blockIdx.y;
    int i0 = blockIdx.x * 32;
    int lane = threadIdx.x;
    int row = threadIdx.y;
#pragma unroll
    for (int r = 0; r < 4; r++) {
        int b = row * 4 + r;
        tile[b][lane] = x[((size_t)b * TT + t) * II + i0 + lane];
    }
    __syncthreads();
#pragma unroll
    for (int r = 0; r < 4; r++) {
        int ii = row * 4 + r;
        g_xT[((size_t)t * II + i0 + ii) * BB + lane] = tile[lane][ii];
    }
}

// ---------------- prologue: h0 (2,B,H) -> [k][b] ping buffers ----------------
__global__ void k_init_h(const float* __restrict__ h0) {
    int idx = blockIdx.x * blockDim.x + threadIdx.x;
    if (idx < HH * BB) {
        int k = idx / BB;
        int b = idx % BB;
        g_h0buf[0][idx] = h0[(size_t)0 * BB * HH + (size_t)b * HH + k];
        g_h1buf[0][idx] = h0[(size_t)1 * BB * HH + (size_t)b * HH + k];
    }
}

// ---------------- prologue: transpose weights into per-CTA [k4][j][4] blocks ----
__global__ void k_wT(const float* __restrict__ W_z0, const float* __restrict__ W_in0,
                     const float* __restrict__ U_z0, const float* __restrict__ W_res0,
                     const float* __restrict__ W_z1, const float* __restrict__ U_z1,
                     const float* __restrict__ W_in1, const float* __restrict__ W_res1)
{
    const int cta = blockIdx.x;
    const int mat = blockIdx.y;
    const float* src; int K; int off;
    switch (mat) {
        case 0: src = W_z0;   K = II; off = 0;     break;
        case 1: src = W_in0;  K = II; off = 1024;  break;
        case 2: src = U_z0;   K = HH; off = 2048;  break;
        case 3: src = W_res0; K = HH; off = 4096;  break;
        case 4: src = W_z1;   K = HH; off = 6144;  break;
        case 5: src = U_z1;   K = HH; off = 8192;  break;
        case 6: src = W_in1;  K = HH; off = 10240; break;
        default: src = W_res1; K = HH; off = 12288; break;
    }
    const float4* s4 = (const float4*)src;
    float4* d4 = g_wT4 + (size_t)cta * 14336 + off;
    const int nk4 = K / 4;
    for (int u = threadIdx.x; u < nk4 * 8; u += blockDim.x) {
        const int jr = u / nk4;
        const int k4 = u - jr * nk4;
        d4[k4 * 8 + jr] = s4[(size_t)(cta * 8 + jr) * nk4 + k4];
    }
}

// ---------------- main persistent kernel ----------------
__global__ void __launch_bounds__(NTHREADS, 1) k_esgp(
    const float* __restrict__ b_z0, const float* __restrict__ b_z1,
    float* __restrict__ out)
{
    const int tid = threadIdx.x;
    const int cta = blockIdx.x;
    const int kh   = tid >> 5;          // warp id = k-slice (0..7)
    const int lane = tid & 31;
    const int jg = lane >> 3, jh = (lane >> 2) & 1, bq = lane & 3;
    const int j = jg * 2 + jh;          // neuron within CTA (0..7)

    // epilogue identity: (je, be) covers all 8 j x 32 b
    const int je = tid >> 5;
    const int be = tid & 31;
    const int el = (je >> 1) * 8 + (je & 1) * 4 + (be >> 3);
    const int ep = (be >> 1) & 3;
    const int eh = be & 1;
    const int ejg = cta * JPC + je;
    const float bz0e = b_z0[ejg];
    const float bz1e = b_z1[ejg];

    __shared__ float2 s_red[8][32][9];   // [kh][lane][slot] slots 0..3 z, 4..7 h~
    __shared__ float  s_out[8][33];

    const float4* __restrict__ wt = g_wT4 + (size_t)cta * 14336;

    for (int t = 0; t < TT; ++t) {
        const int cur = t & 1, nxt = cur ^ 1;
        ull az0=0,az1=0,az2=0,az3=0, ah0=0,ah1=0,ah2=0,ah3=0;

        // ===== layer 0 : x projection (this warp: i in [kh*64, kh*64+64)) =====
        {
            const float4* xp = (const float4*)g_xT + (size_t)t * (II * BB / 4) + bq * 2;
#pragma unroll 4
            for (int u = 0; u < 16; ++u) {
                const int i4 = kh * 16 + u;
                F4 w0, w1;
                w0.v = wt[i4 * 8 + j];
                w1.v = wt[1024 + i4 * 8 + j];
#pragma unroll
                for (int cc = 0; cc < 4; ++cc) {
                    F4 A, Bv;
                    A.v  = xp[(i4 * 4 + cc) * 8];
                    Bv.v = xp[(i4 * 4 + cc) * 8 + 1];
                    ull W0 = dup2(w0.f[cc]), W1 = dup2(w1.f[cc]);
                    ffma2(az0, W0, A.u[0]);  ffma2(az1, W0, A.u[1]);
                    ffma2(az2, W0, Bv.u[0]); ffma2(az3, W0, Bv.u[1]);
                    ffma2(ah0, W1, A.u[0]);  ffma2(ah1, W1, A.u[1]);
                    ffma2(ah2, W1, Bv.u[0]); ffma2(ah3, W1, Bv.u[1]);
                }
            }
        }
        // ===== layer 0 : recurrent (k in [kh*128, kh*128+128)) =====
        {
            const float4* hb = (const float4*)g_h0buf[cur] + bq * 2;
#pragma unroll 4
            for (int u = 0; u < 32; ++u) {
                const int k4 = kh * 32 + u;
                F4 w0, w1;
                w0.v = wt[2048 + k4 * 8 + j];
                w1.v = wt[4096 + k4 * 8 + j];
#pragma unroll
                for (int cc = 0; cc < 4; ++cc) {
                    F4 A, Bv;
                    A.v  = __ldcg(hb + (k4 * 4 + cc) * 8);
                    Bv.v = __ldcg(hb + (k4 * 4 + cc) * 8 + 1);
                    ull W0 = dup2(w0.f[cc]), W1 = dup2(w1.f[cc]);
                    ffma2(az0, W0, A.u[0]);  ffma2(az1, W0, A.u[1]);
                    ffma2(az2, W0, Bv.u[0]); ffma2(az3, W0, Bv.u[1]);
                    ffma2(ah0, W1, A.u[0]);  ffma2(ah1, W1, A.u[1]);
                    ffma2(ah2, W1, Bv.u[0]); ffma2(ah3, W1, Bv.u[1]);
                }
            }
        }
        // ---- reduce over kh + gate ----
        {
            F2U c;
            c.u = az0; s_red[kh][lane][0] = c.f;  c.u = az1; s_red[kh][lane][1] = c.f;
            c.u = az2; s_red[kh][lane][2] = c.f;  c.u = az3; s_red[kh][lane][3] = c.f;
            c.u = ah0; s_red[kh][lane][4] = c.f;  c.u = ah1; s_red[kh][lane][5] = c.f;
            c.u = ah2; s_red[kh][lane][6] = c.f;  c.u = ah3; s_red[kh][lane][7] = c.f;
        }
        __syncthreads();
        {
            float vz = 0.f, vh = 0.f;
#pragma unroll
            for (int kk = 0; kk < 8; ++kk) {
                vz += ((const float*)&s_red[kk][el][ep])[eh];
                vh += ((const float*)&s_red[kk][el][4 + ep])[eh];
            }
            float z   = 1.f / (1.f + expf(-(vz + bz0e)));
            float htl = tanhf(vh);
            float hc  = __ldcg(&g_h0buf[cur][ejg * BB + be]);
            __stcg(&g_h0buf[nxt][ejg * BB + be], (1.f - z) * hc + z * htl);
        }
        gridbar();   // layer-0 state published

        // ===== layer 1 =====
        az0=0; az1=0; az2=0; az3=0; ah0=0; ah1=0; ah2=0; ah3=0;
        {
            const float4* pb = (const float4*)g_h0buf[nxt] + bq * 2;
            const float4* qb = (const float4*)g_h1buf[cur] + bq * 2;
#pragma unroll 2
            for (int u = 0; u < 32; ++u) {
                const int k4 = kh * 32 + u;
                F4 wz, uz, wi, wr;
                wz.v = wt[6144  + k4 * 8 + j];
                uz.v = wt[8192  + k4 * 8 + j];
                wi.v = wt[10240 + k4 * 8 + j];
                wr.v = wt[12288 + k4 * 8 + j];
#pragma unroll
                for (int cc = 0; cc < 4; ++cc) {
                    F4 Pa, Pb, Qa, Qb;
                    Pa.v = __ldcg(pb + (k4 * 4 + cc) * 8);
                    Pb.v = __ldcg(pb + (k4 * 4 + cc) * 8 + 1);
                    Qa.v = __ldcg(qb + (k4 * 4 + cc) * 8);
                    Qb.v = __ldcg(qb + (k4 * 4 + cc) * 8 + 1);
                    ull WZ = dup2(wz.f[cc]), UZ = dup2(uz.f[cc]);
                    ull WI = dup2(wi.f[cc]), WR = dup2(wr.f[cc]);
                    ffma2(az0, WZ, Pa.u[0]);  ffma2(az1, WZ, Pa.u[1]);
                    ffma2(az2, WZ, Pb.u[0]);  ffma2(az3, WZ, Pb.u[1]);
                    ffma2(az0, UZ, Qa.u[0]);  ffma2(az1, UZ, Qa.u[1]);
                    ffma2(az2, UZ, Qb.u[0]);  ffma2(az3, UZ, Qb.u[1]);
                    ffma2(ah0, WI, Pa.u[0]);  ffma2(ah1, WI, Pa.u[1]);
                    ffma2(ah2, WI, Pb.u[0]);  ffma2(ah3, WI, Pb.u[1]);
                    ffma2(ah0, WR, Qa.u[0]);  ffma2(ah1, WR, Qa.u[1]);
                    ffma2(ah2, WR, Qb.u[0]);  ffma2(ah3, WR, Qb.u[1]);
                }
            }
        }
        {
            F2U c;
            c.u = az0; s_red[kh][lane][0] = c.f;  c.u = az1; s_red[kh][lane][1] = c.f;
            c.u = az2; s_red[kh][lane][2] = c.f;  c.u = az3; s_red[kh][lane][3] = c.f;
            c.u = ah0; s_red[kh][lane][4] = c.f;  c.u = ah1; s_red[kh][lane][5] = c.f;
            c.u = ah2; s_red[kh][lane][6] = c.f;  c.u = ah3; s_red[kh][lane][7] = c.f;
        }
        __syncthreads();
        {
            float vz = 0.f, vh = 0.f;
#pragma unroll
            for (int kk = 0; kk < 8; ++kk) {
                vz += ((const float*)&s_red[kk][el][ep])[eh];
                vh += ((const float*)&s_red[kk][el][4 + ep])[eh];
            }
            float z   = 1.f / (1.f + expf(-(vz + bz1e)));
            float htl = tanhf(vh);
            float hc  = __ldcg(&g_h1buf[cur][ejg * BB + be]);
            float hn  = (1.f - z) * hc + z * htl;
            __stcg(&g_h1buf[nxt][ejg * BB + be], hn);
            s_out[je][be] = hn;
        }
        __syncthreads();
        out[((size_t)(tid >> 3) * TT + t) * HH + cta * JPC + (tid & 7)]
            = s_out[tid & 7][tid >> 3];
        gridbar();   // layer-1 state published
    }

    // ---- h_n tail: final state lives in buf[0] (T even) ----
    {
        const int bo = tid >> 3, jo = tid & 7;
        const int jg2 = cta * JPC + jo;
        const size_t base = (size_t)BB * TT * HH;
        out[base + (size_t)bo * HH + jg2] = __ldcg(&g_h0buf[0][jg2 * BB + bo]);
        out[base + (size_t)BB * HH + (size_t)bo * HH + jg2] = __ldcg(&g_h1buf[0][jg2 * BB + bo]);
    }
}

// ---------------- launcher ----------------
extern "C" void kernel_launch(void* const* d_in, const int* in_sizes, int n_in,
                              void* d_out, int out_size) {
    const float* x      = (const float*)d_in[0];
    const float* h0     = (const float*)d_in[1];
    const float* W_in0  = (const float*)d_in[2];
    const float* W_res0 = (const float*)d_in[3];
    const float* W_z0   = (const float*)d_in[4];
    const float* U_z0   = (const float*)d_in[5];
    const float* b_z0   = (const float*)d_in[6];
    const float* W_in1  = (const float*)d_in[7];
    const float* W_res1 = (const float*)d_in[8];
    const float* W_z1   = (const float*)d_in[9];
    const float* U_z1   = (const float*)d_in[10];
    const float* b_z1   = (const float*)d_in[11];
    float* out = (float*)d_out;

    dim3 tb(32, 8);
    dim3 tg(II / 32, TT);
    k_transpose_x<<<tg, tb>>>(x);
    k_init_h<<<(HH * BB + 255) / 256, 256>>>(h0);
    k_wT<<<dim3(GCTA, 8), 256>>>(W_z0, W_in0, U_z0, W_res0, W_z1, U_z1, W_in1, W_res1);
    k_esgp<<<GCTA, NTHREADS>>>(b_z0, b_z1, out);
}

// round 4
// speedup vs baseline: 1.8016x; 1.5031x over previous
#include <cuda_runtime.h>
#include <math.h>

#define BB 32
#define TT 1024
#define II 512
#define HH 1024
#define GCTA 128
#define NT 512

typedef unsigned long long ull;

// ---------------- device global scratch ----------------
__device__ float  g_xT[(size_t)TT * II * BB];          // x transposed [t][i][b]
__device__ float4 g_wp[(size_t)GCTA * 3 * 512 * 8];    // loop weights, pair-packed
__device__ float4 g_wpx[(size_t)128 * 256 * 8];        // x-proj weights, pair-packed
__device__ ull    g_gx[(size_t)TT * HH * BB];          // precomputed x-gates (z,h~) packed
__device__ float  g_h0buf[2][HH * BB];                 // layer0 h [k][b] ping-pong
__device__ float  g_h1buf[2][HH * BB];                 // layer1 h [k][b] ping-pong
__device__ unsigned g_cnt = 0;
__device__ unsigned g_gen = 0;

// ---------------- packed f32x2 helpers ----------------
__device__ __forceinline__ ull dup2(float w) {
    ull r; asm("mov.b64 %0, {%1, %1};" : "=l"(r) : "f"(w)); return r;
}
__device__ __forceinline__ void ffma2(ull &d, ull a, ull b) {
    asm("fma.rn.f32x2 %0, %1, %2, %0;" : "+l"(d) : "l"(a), "l"(b));
}
__device__ __forceinline__ ull add2(ull a, ull b) {
    ull d; asm("add.rn.f32x2 %0, %1, %2;" : "=l"(d) : "l"(a), "l"(b)); return d;
}
__device__ __forceinline__ void unpack2(ull v, float &lo, float &hi) {
    asm("mov.b64 {%0, %1}, %2;" : "=f"(lo), "=f"(hi) : "l"(v));
}

// ---------------- grid barrier ----------------
__device__ __forceinline__ void gridbar() {
    __syncthreads();
    if (threadIdx.x == 0) {
        __threadfence();
        unsigned g = *((volatile unsigned*)&g_gen);
        unsigned a = atomicAdd(&g_cnt, 1u);
        if (a == GCTA - 1u) {
            g_cnt = 0u;
            __threadfence();
            atomicExch(&g_gen, g + 1u);
        } else {
            while (*((volatile unsigned*)&g_gen) == g) { }
        }
        __threadfence();
    }
    __syncthreads();
}

// ---------------- prologue: transpose x (B,T,I) -> xT[t][i][b] ----------------
__global__ void k_transpose_x(const float* __restrict__ x) {
    __shared__ float tile[32][33];
    int t = blockIdx.y;
    int i0 = blockIdx.x * 32;
    int lane = threadIdx.x;
    int row = threadIdx.y;
#pragma unroll
    for (int r = 0; r < 4; r++) {
        int b = row * 4 + r;
        tile[b][lane] = x[((size_t)b * TT + t) * II + i0 + lane];
    }
    __syncthreads();
#pragma unroll
    for (int r = 0; r < 4; r++) {
        int ii = row * 4 + r;
        g_xT[((size_t)t * II + i0 + ii) * BB + lane] = tile[lane][ii];
    }
}

// ---------------- prologue: h0 (2,B,H) -> [k][b] ping buffers ----------------
__global__ void k_init_h(const float* __restrict__ h0) {
    int idx = blockIdx.x * blockDim.x + threadIdx.x;
    if (idx < HH * BB) {
        int k = idx / BB;
        int b = idx % BB;
        g_h0buf[0][idx] = h0[(size_t)0 * BB * HH + (size_t)b * HH + k];
        g_h1buf[0][idx] = h0[(size_t)1 * BB * HH + (size_t)b * HH + k];
    }
}

// ---------------- prologue: pack loop weights (pairs interleaved) ----------------
__global__ void k_pack_main(const float* __restrict__ U_z0, const float* __restrict__ W_res0,
                            const float* __restrict__ W_z1, const float* __restrict__ U_z1,
                            const float* __restrict__ W_in1, const float* __restrict__ W_res1)
{
    int idx = blockIdx.x * blockDim.x + threadIdx.x;
    if (idx >= GCTA * 3 * 512 * 8) return;
    int j  = idx & 7;
    int r  = idx >> 3;
    int k2 = r & 511;
    r >>= 9;
    int p   = r % 3;
    int cta = r / 3;
    const float* m0; const float* m1;
    if (p == 0)      { m0 = U_z0; m1 = W_res0; }
    else if (p == 1) { m0 = W_z1; m1 = W_in1;  }
    else             { m0 = U_z1; m1 = W_res1; }
    size_t row = (size_t)(cta * 8 + j) * HH;
    float4 v;
    v.x = m0[row + 2 * k2];     v.y = m1[row + 2 * k2];
    v.z = m0[row + 2 * k2 + 1]; v.w = m1[row + 2 * k2 + 1];
    g_wp[idx] = v;
}

// ---------------- prologue: pack x-projection weights ----------------
__global__ void k_pack_x(const float* __restrict__ W_z0, const float* __restrict__ W_in0) {
    int idx = blockIdx.x * blockDim.x + threadIdx.x;
    if (idx >= 128 * 256 * 8) return;
    int j  = idx & 7;
    int r  = idx >> 3;
    int k2 = r & 255;
    int jb = r >> 8;
    size_t row = (size_t)(jb * 8 + j) * II;
    float4 v;
    v.x = W_z0[row + 2 * k2];     v.y = W_in0[row + 2 * k2];
    v.z = W_z0[row + 2 * k2 + 1]; v.w = W_in0[row + 2 * k2 + 1];
    g_wpx[idx] = v;
}

// ---------------- precompute x-gates: g_gx[t][j][b] = (Wz0.x, Win0.x) packed -----
__global__ void __launch_bounds__(256, 1) k_gx(const float* __restrict__ dummy) {
    extern __shared__ ull sm_gx[];
    ulonglong2* sw = (ulonglong2*)sm_gx;  // 2048 entries (32KB)
    ull*        pr = sm_gx + 4096;        // [w][j][b] 2048 ull (16KB)

    const int jb = blockIdx.x;            // 0..127
    const int tb = blockIdx.y;            // 0..127
    const int tid = threadIdx.x;
    const int w = tid >> 5;
    const int lane = tid & 31;

    const float4* src = g_wpx + (size_t)jb * 2048;
#pragma unroll
    for (int u = 0; u < 8; u++) ((float4*)sw)[tid + u * 256] = src[tid + u * 256];
    __syncthreads();

    for (int tt = 0; tt < 8; tt++) {
        const int t = tb * 8 + tt;
        ull acc[8];
#pragma unroll
        for (int j = 0; j < 8; j++) acc[j] = 0;
        const float* xp = g_xT + (size_t)t * II * BB;
#pragma unroll 4
        for (int u = 0; u < 32; u++) {
            const int k2 = w * 32 + u;
            ull A0 = dup2(__ldg(xp + (2 * k2) * BB + lane));
            ull A1 = dup2(__ldg(xp + (2 * k2 + 1) * BB + lane));
#pragma unroll
            for (int j = 0; j < 8; j++) {
                ulonglong2 wv = sw[k2 * 8 + j];
                ffma2(acc[j], wv.x, A0);
                ffma2(acc[j], wv.y, A1);
            }
        }
#pragma unroll
        for (int j = 0; j < 8; j++) pr[w * 256 + j * 32 + lane] = acc[j];
        __syncthreads();
        if (tid < 256) {
            const int e_j = tid >> 5;
            const int e_b = tid & 31;
            ull s = pr[e_j * 32 + e_b];
#pragma unroll
            for (int ww = 1; ww < 8; ww++) s = add2(s, pr[ww * 256 + e_j * 32 + e_b]);
            g_gx[((size_t)t * HH + jb * 8 + e_j) * BB + e_b] = s;
        }
        __syncthreads();
    }
}

// ---------------- main persistent kernel ----------------
#define SMEM_BYTES (230400)
__global__ void __launch_bounds__(NT, 1) k_esgp(
    const float* __restrict__ b_z0, const float* __restrict__ b_z1,
    float* __restrict__ out)
{
    extern __shared__ ull sm[];
    ulonglong2* sw   = (ulonglong2*)sm;  // 12288 ulonglong2 = 192KB, 3 pairs of 4096
    ull*   s_red = sm + 24576;           // [kh][j][b] = 4096 ull = 32KB
    float* s_out = (float*)(sm + 28672); // 256 floats

    const int tid = threadIdx.x;
    const int cta = blockIdx.x;
    const int kh = tid >> 5;             // warp 0..15 = k-slice
    const int lane = tid & 31;           // = batch b

    // preload weights into SMEM (once)
    {
        const float4* src = g_wp + (size_t)cta * 12288;
        for (int i = tid; i < 12288; i += NT) ((float4*)sw)[i] = src[i];
    }
    __syncthreads();

    // epilogue identity (first 256 threads)
    const int e_j = tid >> 5;            // valid when tid<256: 0..7
    const int e_b = tid & 31;
    const int ejg = cta * 8 + e_j;
    float bz0e = 0.f, bz1e = 0.f;
    if (tid < 256) { bz0e = b_z0[ejg]; bz1e = b_z1[ejg]; }

    for (int t = 0; t < TT; t++) {
        const int cur = t & 1, nxt = cur ^ 1;
        ull acc[8];

        // ===== layer 0 recurrent: pair0 (U_z0, W_res0) over h0[cur] =====
#pragma unroll
        for (int j = 0; j < 8; j++) acc[j] = 0;
        {
            const float* hb = g_h0buf[cur];
#pragma unroll 4
            for (int u = 0; u < 32; u++) {
                const int k2 = kh * 32 + u;
                ull A0 = dup2(__ldcg(hb + (2 * k2) * BB + lane));
                ull A1 = dup2(__ldcg(hb + (2 * k2 + 1) * BB + lane));
#pragma unroll
                for (int j = 0; j < 8; j++) {
                    ulonglong2 wv = sw[k2 * 8 + j];
                    ffma2(acc[j], wv.x, A0);
                    ffma2(acc[j], wv.y, A1);
                }
            }
        }
#pragma unroll
        for (int j = 0; j < 8; j++) s_red[kh * 256 + j * 32 + lane] = acc[j];
        __syncthreads();
        if (tid < 256) {
            ull s = s_red[e_j * 32 + e_b];
#pragma unroll
            for (int kk = 1; kk < 16; kk++) s = add2(s, s_red[kk * 256 + e_j * 32 + e_b]);
            s = add2(s, __ldg(&g_gx[((size_t)t * HH + ejg) * BB + e_b]));
            float vz, vh; unpack2(s, vz, vh);
            float z   = 1.f / (1.f + expf(-(vz + bz0e)));
            float htl = tanhf(vh);
            float hc  = __ldcg(&g_h0buf[cur][ejg * BB + e_b]);
            __stcg(&g_h0buf[nxt][ejg * BB + e_b], (1.f - z) * hc + z * htl);
        }
        gridbar();   // the only grid barrier per step

        // ===== layer 1: pair1 (W_z1,W_in1) over h0[nxt], pair2 (U_z1,W_res1) over h1[cur]
#pragma unroll
        for (int j = 0; j < 8; j++) acc[j] = 0;
        {
            const float* pbuf = g_h0buf[nxt];
            const float* qbuf = g_h1buf[cur];
#pragma unroll 2
            for (int u = 0; u < 32; u++) {
                const int k2 = kh * 32 + u;
                ull A0 = dup2(__ldcg(pbuf + (2 * k2) * BB + lane));
                ull A1 = dup2(__ldcg(pbuf + (2 * k2 + 1) * BB + lane));
                ull B0 = dup2(__ldcg(qbuf + (2 * k2) * BB + lane));
                ull B1 = dup2(__ldcg(qbuf + (2 * k2 + 1) * BB + lane));
#pragma unroll
                for (int j = 0; j < 8; j++) {
                    ulonglong2 w1 = sw[4096 + k2 * 8 + j];
                    ulonglong2 w2 = sw[8192 + k2 * 8 + j];
                    ffma2(acc[j], w1.x, A0);
                    ffma2(acc[j], w1.y, A1);
                    ffma2(acc[j], w2.x, B0);
                    ffma2(acc[j], w2.y, B1);
                }
            }
        }
#pragma unroll
        for (int j = 0; j < 8; j++) s_red[kh * 256 + j * 32 + lane] = acc[j];
        __syncthreads();
        if (tid < 256) {
            ull s = s_red[e_j * 32 + e_b];
#pragma unroll
            for (int kk = 1; kk < 16; kk++) s = add2(s, s_red[kk * 256 + e_j * 32 + e_b]);
            float vz, vh; unpack2(s, vz, vh);
            float z   = 1.f / (1.f + expf(-(vz + bz1e)));
            float htl = tanhf(vh);
            float hc  = __ldcg(&g_h1buf[cur][ejg * BB + e_b]);
            float hn  = (1.f - z) * hc + z * htl;
            __stcg(&g_h1buf[nxt][ejg * BB + e_b], hn);
            s_out[e_j * 32 + e_b] = hn;
        }
        __syncthreads();
        if (tid < 256) {   // coalesced-by-j output write: out[b][t][cta*8+j]
            int b = tid >> 3, j = tid & 7;
            out[((size_t)b * TT + t) * HH + cta * 8 + j] = s_out[j * 32 + b];
        }
        __syncthreads();   // protect s_red/s_out reuse next step
    }

    // ---- h_n tail: final state parity 0 (T even) ----
    if (tid < 256) {
        const int jg2 = cta * 8 + e_j;
        const size_t base = (size_t)BB * TT * HH;
        out[base + (size_t)e_b * HH + jg2] = __ldcg(&g_h0buf[0][jg2 * BB + e_b]);
        out[base + (size_t)BB * HH + (size_t)e_b * HH + jg2] = __ldcg(&g_h1buf[0][jg2 * BB + e_b]);
    }
}

// ---------------- launcher ----------------
extern "C" void kernel_launch(void* const* d_in, const int* in_sizes, int n_in,
                              void* d_out, int out_size) {
    const float* x      = (const float*)d_in[0];
    const float* h0     = (const float*)d_in[1];
    const float* W_in0  = (const float*)d_in[2];
    const float* W_res0 = (const float*)d_in[3];
    const float* W_z0   = (const float*)d_in[4];
    const float* U_z0   = (const float*)d_in[5];
    const float* b_z0   = (const float*)d_in[6];
    const float* W_in1  = (const float*)d_in[7];
    const float* W_res1 = (const float*)d_in[8];
    const float* W_z1   = (const float*)d_in[9];
    const float* U_z1   = (const float*)d_in[10];
    const float* b_z1   = (const float*)d_in[11];
    float* out = (float*)d_out;

    static int configured = 0;
    if (!configured) {
        cudaFuncSetAttribute(k_esgp, cudaFuncAttributeMaxDynamicSharedMemorySize, SMEM_BYTES);
        cudaFuncSetAttribute(k_gx, cudaFuncAttributeMaxDynamicSharedMemorySize, 49152);
        configured = 1;
    }

    dim3 tb(32, 8);
    dim3 tg(II / 32, TT);
    k_transpose_x<<<tg, tb>>>(x);
    k_init_h<<<(HH * BB + 255) / 256, 256>>>(h0);
    k_pack_main<<<(GCTA * 3 * 512 * 8 + 255) / 256, 256>>>(U_z0, W_res0, W_z1, U_z1, W_in1, W_res1);
    k_pack_x<<<(128 * 256 * 8 + 255) / 256, 256>>>(W_z0, W_in0);
    k_gx<<<dim3(128, 128), 256, 49152>>>(x);
    k_esgp<<<GCTA, NT, SMEM_BYTES>>>(b_z0, b_z1, out);
}